// round 1
// baseline (speedup 1.0000x reference)
#include <cuda_runtime.h>

// ---------------- problem-size constants (fixed by the dataset) -------------
#define N_MAX   100032      // >= 100000 nodes
#define E_MAX   1600000     // edges
#define D       50          // attrs
#define STR     64          // padded row stride of internal buffers (256B)
#define NITER   30
#define SCAN_B  256

// ---------------- static device scratch (no allocations allowed) ------------
__device__ int   g_deg[N_MAX];
__device__ int   g_offs[N_MAX + 1];
__device__ int   g_cursor[N_MAX];
__device__ int   g_partial[512];
__device__ int2  g_csr[E_MAX];            // {col*STR, bits(w)}
__device__ float g_dinv[N_MAX];
__device__ unsigned char g_isknown[N_MAX];
__device__ float g_meansum[64];
__device__ float g_mean[64];              // pads [50,64) stay 0 forever
__device__ float g_alpha[64];
__device__ float g_oma[64];
__device__ float g_beta[64];
__device__ float g_omb[64];
__device__ float g_colsum[(NITER + 1) * 64];
__device__ int   g_need_colmean;
__device__ int   g_need_beta;
__device__ float g_bufA[(size_t)N_MAX * STR];
__device__ float g_bufB[(size_t)N_MAX * STR];

// ---------------- prologue kernels ------------------------------------------
__global__ void k_zero(int n) {
    int i = blockIdx.x * blockDim.x + threadIdx.x;
    if (i < n) { g_deg[i] = 0; g_isknown[i] = 0; }
    if (i < 64) g_meansum[i] = 0.f;
    if (i < (NITER + 1) * 64) g_colsum[i] = 0.f;
}

__global__ void k_deg(const int* __restrict__ row, int E) {
    int e = blockIdx.x * blockDim.x + threadIdx.x;
    if (e < E) atomicAdd(&g_deg[row[e]], 1);
}

__global__ void k_dinv(int n) {
    int i = blockIdx.x * blockDim.x + threadIdx.x;
    if (i < n) {
        int dg = g_deg[i];
        g_dinv[i] = (dg > 0) ? rsqrtf((float)dg) : 0.f;
    }
}

// block-level exclusive scan of g_deg -> g_offs, block totals -> g_partial
__global__ void k_scan1(int n) {
    __shared__ int s[SCAN_B];
    int i = blockIdx.x * SCAN_B + threadIdx.x;
    int v = (i < n) ? g_deg[i] : 0;
    s[threadIdx.x] = v;
    __syncthreads();
    for (int d = 1; d < SCAN_B; d <<= 1) {
        int t = (threadIdx.x >= d) ? s[threadIdx.x - d] : 0;
        __syncthreads();
        s[threadIdx.x] += t;
        __syncthreads();
    }
    if (i < n) g_offs[i] = s[threadIdx.x] - v;   // exclusive
    if (threadIdx.x == SCAN_B - 1) g_partial[blockIdx.x] = s[SCAN_B - 1];
}

__global__ void k_scan2(int nb) {
    __shared__ int s[512];
    int v = (threadIdx.x < nb) ? g_partial[threadIdx.x] : 0;
    s[threadIdx.x] = v;
    __syncthreads();
    for (int d = 1; d < 512; d <<= 1) {
        int t = (threadIdx.x >= d) ? s[threadIdx.x - d] : 0;
        __syncthreads();
        s[threadIdx.x] += t;
        __syncthreads();
    }
    if (threadIdx.x < nb) g_partial[threadIdx.x] = s[threadIdx.x] - v;  // exclusive
}

__global__ void k_scan3(int n, int E) {
    int i = blockIdx.x * SCAN_B + threadIdx.x;
    if (i < n) {
        int o = g_offs[i] + g_partial[blockIdx.x];
        g_offs[i] = o;
        g_cursor[i] = o;
    }
    if (i == 0) g_offs[n] = E;
}

__global__ void k_scatter(const int* __restrict__ row, const int* __restrict__ col, int E) {
    int e = blockIdx.x * blockDim.x + threadIdx.x;
    if (e < E) {
        int r = row[e], c = col[e];
        int p = atomicAdd(&g_cursor[r], 1);
        g_csr[p] = make_int2(c * STR, __float_as_int(g_dinv[r] * g_dinv[c]));
    }
}

__global__ void k_isknown(const int* __restrict__ km, int K) {
    int k = blockIdx.x * blockDim.x + threadIdx.x;
    if (k < K) g_isknown[km[k]] = 1;
}

__global__ void k_mean(const float* __restrict__ x, const int* __restrict__ km, int K) {
    __shared__ float sm[64];
    if (threadIdx.x < 64) sm[threadIdx.x] = 0.f;
    __syncthreads();
    int lane = threadIdx.x & 31;
    int w  = (blockIdx.x * blockDim.x + threadIdx.x) >> 5;
    int nw = (gridDim.x * blockDim.x) >> 5;
    float2 acc = make_float2(0.f, 0.f);
    for (int k = w; k < K; k += nw) {
        int idx = km[k];
        if (lane < 25) {
            float2 vv = *(const float2*)(x + (size_t)idx * D + 2 * lane);
            acc.x += vv.x; acc.y += vv.y;
        }
    }
    if (lane < 25) {
        atomicAdd(&sm[2 * lane],     acc.x);
        atomicAdd(&sm[2 * lane + 1], acc.y);
    }
    __syncthreads();
    if (threadIdx.x < D) atomicAdd(&g_meansum[threadIdx.x], sm[threadIdx.x]);
}

__global__ void k_params(const float* __restrict__ eta, const float* __restrict__ theta,
                         int n, int K) {
    __shared__ int fc, fb;
    if (threadIdx.x == 0) { fc = 0; fb = 0; }
    __syncthreads();
    int d = threadIdx.x;
    if (d < D) {
        g_mean[d] = g_meansum[d] / (float)K;
        float nf = (float)n;
        float a  = (nf - 1.f) / (theta[d] * nf + (nf - 1.f));
        float ia = 1.f / a;
        float b  = ia / (ia + eta[d]);
        g_alpha[d] = a;  g_oma[d] = 1.f - a;
        g_beta[d]  = b;  g_omb[d] = 1.f - b;
        if (a != 1.f) atomicExch(&fc, 1);
        if (b != 1.f) atomicExch(&fb, 1);
    }
    __syncthreads();
    if (threadIdx.x == 0) { g_need_colmean = fc; g_need_beta = fb; }
}

// out0[i] = (known ? x[i] : 0) - mean ; also colsum[0] if needed
__global__ void k_init(const float* __restrict__ x, int n) {
    int gw   = (blockIdx.x * blockDim.x + threadIdx.x) >> 5;
    int lane = threadIdx.x & 31;
    __shared__ float cs[64];
    int needc = g_need_colmean;
    if (needc) { if (threadIdx.x < 64) cs[threadIdx.x] = 0.f; __syncthreads(); }
    float2 v = make_float2(0.f, 0.f);
    if (gw < n) {
        if (lane < 25 && g_isknown[gw])
            v = *(const float2*)(x + (size_t)gw * D + 2 * lane);
        float2 m = ((const float2*)g_mean)[lane];
        v.x -= m.x; v.y -= m.y;
        if (lane < 25) *(float2*)(g_bufA + (size_t)gw * STR + 2 * lane) = v;
    }
    if (needc) {
        if (gw < n && lane < 25) {
            atomicAdd(&cs[2 * lane],     v.x);
            atomicAdd(&cs[2 * lane + 1], v.y);
        }
        __syncthreads();
        if (threadIdx.x < D) atomicAdd(&g_colsum[threadIdx.x], cs[threadIdx.x]);
    }
}

// ---------------- the hot loop: one propagation step ------------------------
__global__ __launch_bounds__(256) void k_iter(const float* __restrict__ x,
                                              float* __restrict__ fout,
                                              int n, float invn, int t, int last) {
    int gw   = (blockIdx.x * blockDim.x + threadIdx.x) >> 5;
    int lane = threadIdx.x & 31;
    __shared__ float cs[64];
    const int needc = g_need_colmean;
    if (needc) { if (threadIdx.x < 64) cs[threadIdx.x] = 0.f; __syncthreads(); }

    const float* in  = (t & 1) ? g_bufB : g_bufA;
    float*       out = (t & 1) ? g_bufA : g_bufB;
    const float* cs_in  = g_colsum + t * 64;
    float*       cs_out = g_colsum + (t + 1) * 64;

    float2 v = make_float2(0.f, 0.f);
    if (gw < n) {
        int s = g_offs[gw], e = g_offs[gw + 1];
        const float* inp = in + 2 * lane;
        float2 acc = make_float2(0.f, 0.f);
        int i = s;
        for (; i + 4 <= e; i += 4) {
            int2 c0 = g_csr[i], c1 = g_csr[i + 1], c2 = g_csr[i + 2], c3 = g_csr[i + 3];
            float2 v0 = *(const float2*)(inp + c0.x);
            float2 v1 = *(const float2*)(inp + c1.x);
            float2 v2 = *(const float2*)(inp + c2.x);
            float2 v3 = *(const float2*)(inp + c3.x);
            acc.x = fmaf(__int_as_float(c0.y), v0.x, acc.x);
            acc.y = fmaf(__int_as_float(c0.y), v0.y, acc.y);
            acc.x = fmaf(__int_as_float(c1.y), v1.x, acc.x);
            acc.y = fmaf(__int_as_float(c1.y), v1.y, acc.y);
            acc.x = fmaf(__int_as_float(c2.y), v2.x, acc.x);
            acc.y = fmaf(__int_as_float(c2.y), v2.y, acc.y);
            acc.x = fmaf(__int_as_float(c3.y), v3.x, acc.x);
            acc.y = fmaf(__int_as_float(c3.y), v3.y, acc.y);
        }
        for (; i < e; ++i) {
            int2 c = g_csr[i];
            float2 v0 = *(const float2*)(inp + c.x);
            acc.x = fmaf(__int_as_float(c.y), v0.x, acc.x);
            acc.y = fmaf(__int_as_float(c.y), v0.y, acc.y);
        }
        float2 a = ((const float2*)g_alpha)[lane];
        v.x = a.x * acc.x;
        v.y = a.y * acc.y;
        if (needc) {
            float2 om = ((const float2*)g_oma)[lane];
            float cmx = cs_in[2 * lane] * invn;
            float cmy = cs_in[2 * lane + 1] * invn;
            v.x = fmaf(om.x, cmx, v.x);
            v.y = fmaf(om.y, cmy, v.y);
        }
        if (g_need_beta && g_isknown[gw]) {
            float2 b  = ((const float2*)g_beta)[lane];
            float2 ob = ((const float2*)g_omb)[lane];
            float2 m  = ((const float2*)g_mean)[lane];
            float2 xv = make_float2(0.f, 0.f);
            if (lane < 25) xv = *(const float2*)(x + (size_t)gw * D + 2 * lane);
            v.x = b.x * v.x + ob.x * (xv.x - m.x);
            v.y = b.y * v.y + ob.y * (xv.y - m.y);
        }
        if (last) {
            float2 m = ((const float2*)g_mean)[lane];
            v.x += m.x; v.y += m.y;
            if (lane < 25) *(float2*)(fout + (size_t)gw * D + 2 * lane) = v;
        } else {
            if (lane < 25) *(float2*)(out + (size_t)gw * STR + 2 * lane) = v;
        }
    }
    if (needc && !last) {
        if (gw < n && lane < 25) {
            atomicAdd(&cs[2 * lane],     v.x);
            atomicAdd(&cs[2 * lane + 1], v.y);
        }
        __syncthreads();
        if (threadIdx.x < D) atomicAdd(&cs_out[threadIdx.x], cs[threadIdx.x]);
    }
}

// ---------------- launcher ---------------------------------------------------
extern "C" void kernel_launch(void* const* d_in, const int* in_sizes, int n_in,
                              void* d_out, int out_size) {
    const float* x     = (const float*)d_in[0];
    const float* eta   = (const float*)d_in[1];
    const float* theta = (const float*)d_in[2];
    const int*   ei    = (const int*)d_in[3];
    const int*   km    = (const int*)d_in[4];

    int dd = in_sizes[1];              // 50
    int n  = in_sizes[0] / dd;         // 100000
    int E  = in_sizes[3] / 2;          // 1600000
    int K  = in_sizes[4];              // 50000
    const int* row = ei;
    const int* col = ei + E;

    const int TB = 256;
    int nbN = (n + TB - 1) / TB;
    int nbE = (E + TB - 1) / TB;
    int nbK = (K + TB - 1) / TB;
    int nbW = (n * 32 + TB - 1) / TB;  // warp-per-node grids

    k_zero   <<<nbN, TB>>>(n);
    k_deg    <<<nbE, TB>>>(row, E);
    k_dinv   <<<nbN, TB>>>(n);
    k_scan1  <<<nbN, TB>>>(n);
    k_scan2  <<<1, 512>>>(nbN);
    k_scan3  <<<nbN, TB>>>(n, E);
    k_scatter<<<nbE, TB>>>(row, col, E);
    k_isknown<<<nbK, TB>>>(km, K);
    k_mean   <<<100, 256>>>(x, km, K);
    k_params <<<1, 64>>>(eta, theta, n, K);
    k_init   <<<nbW, TB>>>(x, n);

    float invn = 1.f / (float)n;
    for (int t = 0; t < NITER; ++t) {
        k_iter<<<nbW, TB>>>(x, (float*)d_out, n, invn, t, (t == NITER - 1) ? 1 : 0);
    }
}

// round 2
// speedup vs baseline: 1.8064x; 1.8064x over previous
#include <cuda_runtime.h>
#include <cuda_fp16.h>

// ---------------- problem-size constants (fixed by the dataset) -------------
#define N_MAX   100032      // >= 100000 nodes
#define E_MAX   1600000     // edges
#define D       50          // attrs
#define STRH    64          // padded row stride of fp16 buffers (64 halves = 128B)
#define NITER   30
#define SCAN_B  256

// ---------------- static device scratch (no allocations allowed) ------------
__device__ int    g_deg[N_MAX];
__device__ int    g_offs[N_MAX + 1];
__device__ int    g_cursor[N_MAX];
__device__ int    g_partial[512];
__device__ int2   g_csr[E_MAX];            // {col*STRH (half offset), bits(w)}
__device__ float  g_dinv[N_MAX];
__device__ unsigned char g_isknown[N_MAX];
__device__ float  g_meansum[64];
__device__ float  g_mean[64];              // pads [50,64) stay 0 forever
__device__ float  g_alpha[64];
__device__ float  g_oma[64];
__device__ float  g_beta[64];
__device__ float  g_omb[64];
__device__ float  g_colsum[(NITER + 1) * 64];
__device__ int    g_need_colmean;
__device__ int    g_need_beta;
__device__ __half g_bufA[(size_t)N_MAX * STRH];   // 12.8 MB
__device__ __half g_bufB[(size_t)N_MAX * STRH];   // 12.8 MB

// ---------------- prologue kernels (merged: 7 launches) ----------------------
// 0: zero everything
__global__ void k_zero(int n) {
    int i = blockIdx.x * blockDim.x + threadIdx.x;
    if (i < n) { g_deg[i] = 0; g_isknown[i] = 0; }
    if (i < 64) g_meansum[i] = 0.f;
    if (i < (NITER + 1) * 64) g_colsum[i] = 0.f;
}

// 1: degree histogram + isknown flags + mean partial sums (independent work)
__global__ void k_deg_known_mean(const int* __restrict__ row,
                                 const int* __restrict__ km,
                                 const float* __restrict__ x, int E, int K) {
    int i = blockIdx.x * blockDim.x + threadIdx.x;
    if (i < E) atomicAdd(&g_deg[row[i]], 1);
    if (i < K) g_isknown[km[i]] = 1;
    // mean over known rows: warps 0..799 (blocks 0..99) stride over K
    if (blockIdx.x < 100) {
        __shared__ float sm[64];
        if (threadIdx.x < 64) sm[threadIdx.x] = 0.f;
        __syncthreads();
        int lane = threadIdx.x & 31;
        int w  = (blockIdx.x * blockDim.x + threadIdx.x) >> 5;
        int nw = (100 * blockDim.x) >> 5;
        float2 acc = make_float2(0.f, 0.f);
        for (int k = w; k < K; k += nw) {
            int idx = km[k];
            if (lane < 25) {
                float2 vv = *(const float2*)(x + (size_t)idx * D + 2 * lane);
                acc.x += vv.x; acc.y += vv.y;
            }
        }
        if (lane < 25) {
            atomicAdd(&sm[2 * lane],     acc.x);
            atomicAdd(&sm[2 * lane + 1], acc.y);
        }
        __syncthreads();
        if (threadIdx.x < D) atomicAdd(&g_meansum[threadIdx.x], sm[threadIdx.x]);
    }
}

// 2: dinv + block-level exclusive scan of g_deg
__global__ void k_scan1(int n) {
    __shared__ int s[SCAN_B];
    int i = blockIdx.x * SCAN_B + threadIdx.x;
    int v = (i < n) ? g_deg[i] : 0;
    if (i < n) g_dinv[i] = (v > 0) ? rsqrtf((float)v) : 0.f;
    s[threadIdx.x] = v;
    __syncthreads();
    for (int d = 1; d < SCAN_B; d <<= 1) {
        int t = (threadIdx.x >= d) ? s[threadIdx.x - d] : 0;
        __syncthreads();
        s[threadIdx.x] += t;
        __syncthreads();
    }
    if (i < n) g_offs[i] = s[threadIdx.x] - v;   // exclusive
    if (threadIdx.x == SCAN_B - 1) g_partial[blockIdx.x] = s[SCAN_B - 1];
}

// 3: scan of block totals + parameter computation (single block)
__global__ void k_scan2_params(int nb, const float* __restrict__ eta,
                               const float* __restrict__ theta, int n, int K) {
    __shared__ int s[512];
    __shared__ int fc, fb;
    int v = (threadIdx.x < nb) ? g_partial[threadIdx.x] : 0;
    s[threadIdx.x] = v;
    if (threadIdx.x == 0) { fc = 0; fb = 0; }
    __syncthreads();
    for (int d = 1; d < 512; d <<= 1) {
        int t = (threadIdx.x >= d) ? s[threadIdx.x - d] : 0;
        __syncthreads();
        s[threadIdx.x] += t;
        __syncthreads();
    }
    if (threadIdx.x < nb) g_partial[threadIdx.x] = s[threadIdx.x] - v;  // exclusive
    int d = threadIdx.x;
    if (d < D) {
        g_mean[d] = g_meansum[d] / (float)K;
        float nf = (float)n;
        float a  = (nf - 1.f) / (theta[d] * nf + (nf - 1.f));
        float ia = 1.f / a;
        float b  = ia / (ia + eta[d]);
        g_alpha[d] = a;  g_oma[d] = 1.f - a;
        g_beta[d]  = b;  g_omb[d] = 1.f - b;
        if (a != 1.f) atomicExch(&fc, 1);
        if (b != 1.f) atomicExch(&fb, 1);
    }
    __syncthreads();
    if (threadIdx.x == 0) { g_need_colmean = fc; g_need_beta = fb; }
}

// 4: finalize offsets + cursors
__global__ void k_scan3(int n, int E) {
    int i = blockIdx.x * SCAN_B + threadIdx.x;
    if (i < n) {
        int o = g_offs[i] + g_partial[blockIdx.x];
        g_offs[i] = o;
        g_cursor[i] = o;
    }
    if (i == 0) g_offs[n] = E;
}

// 5: CSR scatter with precomputed weights
__global__ void k_scatter(const int* __restrict__ row, const int* __restrict__ col, int E) {
    int e = blockIdx.x * blockDim.x + threadIdx.x;
    if (e < E) {
        int r = row[e], c = col[e];
        int p = atomicAdd(&g_cursor[r], 1);
        g_csr[p] = make_int2(c * STRH, __float_as_int(g_dinv[r] * g_dinv[c]));
    }
}

// 6: out0[i] = (known ? x[i] : 0) - mean  -> fp16 buffer; colsum[0] if needed
__global__ void k_init(const float* __restrict__ x, int n) {
    int gw   = (blockIdx.x * blockDim.x + threadIdx.x) >> 5;
    int lane = threadIdx.x & 31;
    __shared__ float cs[64];
    int needc = g_need_colmean;
    if (needc) { if (threadIdx.x < 64) cs[threadIdx.x] = 0.f; __syncthreads(); }
    float2 v = make_float2(0.f, 0.f);
    if (gw < n) {
        if (lane < 25 && g_isknown[gw])
            v = *(const float2*)(x + (size_t)gw * D + 2 * lane);
        float2 m = ((const float2*)g_mean)[lane];
        v.x -= m.x; v.y -= m.y;
        if (lane < 25)
            *(__half2*)(g_bufA + (size_t)gw * STRH + 2 * lane) = __floats2half2_rn(v.x, v.y);
    }
    if (needc) {
        if (gw < n && lane < 25) {
            atomicAdd(&cs[2 * lane],     v.x);
            atomicAdd(&cs[2 * lane + 1], v.y);
        }
        __syncthreads();
        if (threadIdx.x < D) atomicAdd(&g_colsum[threadIdx.x], cs[threadIdx.x]);
    }
}

// ---------------- the hot loop: one propagation step ------------------------
// warp-per-node; lanes 0..24 each own a float2 of the 50 attrs.
// gathers are fp16 (half2), accumulation fp32.
__global__ __launch_bounds__(256) void k_iter(const float* __restrict__ x,
                                              float* __restrict__ fout,
                                              int n, float invn, int t, int last) {
    int gw   = (blockIdx.x * blockDim.x + threadIdx.x) >> 5;
    int lane = threadIdx.x & 31;
    __shared__ float cs[64];
    const int needc = g_need_colmean;
    if (needc) { if (threadIdx.x < 64) cs[threadIdx.x] = 0.f; __syncthreads(); }

    const __half* in  = (t & 1) ? g_bufB : g_bufA;
    __half*       out = (t & 1) ? g_bufA : g_bufB;
    const float* cs_in  = g_colsum + t * 64;
    float*       cs_out = g_colsum + (t + 1) * 64;

    float2 v = make_float2(0.f, 0.f);
    if (gw < n) {
        int s = g_offs[gw], e = g_offs[gw + 1];
        const __half* inp = in + 2 * lane;
        float2 acc = make_float2(0.f, 0.f);
        int i = s;
        for (; i + 4 <= e; i += 4) {
            int2 c0 = g_csr[i], c1 = g_csr[i + 1], c2 = g_csr[i + 2], c3 = g_csr[i + 3];
            float2 v0 = __half22float2(*(const __half2*)(inp + c0.x));
            float2 v1 = __half22float2(*(const __half2*)(inp + c1.x));
            float2 v2 = __half22float2(*(const __half2*)(inp + c2.x));
            float2 v3 = __half22float2(*(const __half2*)(inp + c3.x));
            acc.x = fmaf(__int_as_float(c0.y), v0.x, acc.x);
            acc.y = fmaf(__int_as_float(c0.y), v0.y, acc.y);
            acc.x = fmaf(__int_as_float(c1.y), v1.x, acc.x);
            acc.y = fmaf(__int_as_float(c1.y), v1.y, acc.y);
            acc.x = fmaf(__int_as_float(c2.y), v2.x, acc.x);
            acc.y = fmaf(__int_as_float(c2.y), v2.y, acc.y);
            acc.x = fmaf(__int_as_float(c3.y), v3.x, acc.x);
            acc.y = fmaf(__int_as_float(c3.y), v3.y, acc.y);
        }
        for (; i < e; ++i) {
            int2 c = g_csr[i];
            float2 v0 = __half22float2(*(const __half2*)(inp + c.x));
            acc.x = fmaf(__int_as_float(c.y), v0.x, acc.x);
            acc.y = fmaf(__int_as_float(c.y), v0.y, acc.y);
        }
        float2 a = ((const float2*)g_alpha)[lane];
        v.x = a.x * acc.x;
        v.y = a.y * acc.y;
        if (needc) {
            float2 om = ((const float2*)g_oma)[lane];
            float cmx = cs_in[2 * lane] * invn;
            float cmy = cs_in[2 * lane + 1] * invn;
            v.x = fmaf(om.x, cmx, v.x);
            v.y = fmaf(om.y, cmy, v.y);
        }
        if (g_need_beta && g_isknown[gw]) {
            float2 b  = ((const float2*)g_beta)[lane];
            float2 ob = ((const float2*)g_omb)[lane];
            float2 m  = ((const float2*)g_mean)[lane];
            float2 xv = make_float2(0.f, 0.f);
            if (lane < 25) xv = *(const float2*)(x + (size_t)gw * D + 2 * lane);
            v.x = b.x * v.x + ob.x * (xv.x - m.x);
            v.y = b.y * v.y + ob.y * (xv.y - m.y);
        }
        if (last) {
            float2 m = ((const float2*)g_mean)[lane];
            v.x += m.x; v.y += m.y;
            if (lane < 25) *(float2*)(fout + (size_t)gw * D + 2 * lane) = v;
        } else {
            if (lane < 25)
                *(__half2*)(out + (size_t)gw * STRH + 2 * lane) = __floats2half2_rn(v.x, v.y);
        }
    }
    if (needc && !last) {
        if (gw < n && lane < 25) {
            atomicAdd(&cs[2 * lane],     v.x);
            atomicAdd(&cs[2 * lane + 1], v.y);
        }
        __syncthreads();
        if (threadIdx.x < D) atomicAdd(&cs_out[threadIdx.x], cs[threadIdx.x]);
    }
}

// ---------------- launcher ---------------------------------------------------
extern "C" void kernel_launch(void* const* d_in, const int* in_sizes, int n_in,
                              void* d_out, int out_size) {
    const float* x     = (const float*)d_in[0];
    const float* eta   = (const float*)d_in[1];
    const float* theta = (const float*)d_in[2];
    const int*   ei    = (const int*)d_in[3];
    const int*   km    = (const int*)d_in[4];

    int dd = in_sizes[1];              // 50
    int n  = in_sizes[0] / dd;         // 100000
    int E  = in_sizes[3] / 2;          // 1600000
    int K  = in_sizes[4];              // 50000
    const int* row = ei;
    const int* col = ei + E;

    const int TB = 256;
    int nbN = (n + TB - 1) / TB;
    int nbE = (E + TB - 1) / TB;
    int nbW = (n * 32 + TB - 1) / TB;  // warp-per-node grids

    k_zero          <<<nbN, TB>>>(n);
    k_deg_known_mean<<<nbE, TB>>>(row, km, x, E, K);
    k_scan1         <<<nbN, TB>>>(n);
    k_scan2_params  <<<1, 512>>>(nbN, eta, theta, n, K);
    k_scan3         <<<nbN, TB>>>(n, E);
    k_scatter       <<<nbE, TB>>>(row, col, E);
    k_init          <<<nbW, TB>>>(x, n);

    float invn = 1.f / (float)n;
    for (int t = 0; t < NITER; ++t) {
        k_iter<<<nbW, TB>>>(x, (float*)d_out, n, invn, t, (t == NITER - 1) ? 1 : 0);
    }
}